// round 1
// baseline (speedup 1.0000x reference)
#include <cuda_runtime.h>
#include <cstdint>

#define BQ 16
#define NQ 8400
#define CQ 80
#define GQ 20
#define KQ 1000
#define NPAD 9216      // 9 * 1024
#define NCHUNK 9

#define CONF_THRES 0.25f
#define NMS_IOU 0.45f
#define MATCH_IOU 0.6f
#define MATCH_CONF 0.5f
#define EPSQ 1e-7f

// scratch: sorted 64-bit keys per image (conf<<32 | ~idx<<16 | cls<<8)
__device__ unsigned long long g_keys[BQ * NPAD];

// ---------------------------------------------------------------------------
// Kernel A: per-anchor class max/argmax -> key, then bitonic sort each
// 1024-anchor chunk DESC in shared memory. 144 blocks x 1024 threads.
// ---------------------------------------------------------------------------
__global__ void __launch_bounds__(1024) score_sort_kernel(const float* __restrict__ scores) {
    const int blk = blockIdx.x;
    const int b = blk / NCHUNK;
    const int ch = blk % NCHUNK;
    const int t = threadIdx.x;
    const int n = ch * 1024 + t;

    unsigned long long key = 0ull;
    if (n < NQ) {
        const float4* row = reinterpret_cast<const float4*>(scores) + ((size_t)(b * NQ + n)) * (CQ / 4);
        float best = -1.0f;
        int bc = 0;
#pragma unroll
        for (int c4 = 0; c4 < CQ / 4; ++c4) {
            float4 v = __ldg(row + c4);
            if (v.x > best) { best = v.x; bc = c4 * 4 + 0; }
            if (v.y > best) { best = v.y; bc = c4 * 4 + 1; }
            if (v.z > best) { best = v.z; bc = c4 * 4 + 2; }
            if (v.w > best) { best = v.w; bc = c4 * 4 + 3; }
        }
        float conf = (best >= CONF_THRES) ? best : 0.0f;
        unsigned int cb = __float_as_uint(conf);
        key = ((unsigned long long)cb << 32)
            | ((unsigned long long)(0xFFFFu - (unsigned)n) << 16)
            | ((unsigned long long)(unsigned)bc << 8);
    }

    __shared__ unsigned long long s[1024];
    s[t] = key;

    // bitonic sort 1024 elements, descending
    for (int k = 2; k <= 1024; k <<= 1) {
        for (int j = k >> 1; j > 0; j >>= 1) {
            __syncthreads();
            int ixj = t ^ j;
            if (ixj > t) {
                unsigned long long a = s[t], bb = s[ixj];
                bool desc = ((t & k) == 0);
                if (desc ? (a < bb) : (a > bb)) { s[t] = bb; s[ixj] = a; }
            }
        }
    }
    __syncthreads();
    g_keys[b * NPAD + ch * 1024 + t] = s[t];
}

// ---------------------------------------------------------------------------
// Kernel B: per-image top-1024 merge of 9 sorted chunks, extract top-1000,
// per-class greedy NMS (classes are independent: cross-class IoU == 0 due to
// the MAX_WH class offset), GT matching + stats. 16 blocks x 1024 threads.
// ---------------------------------------------------------------------------
__global__ void __launch_bounds__(1024) select_nms_match_kernel(
    const float* __restrict__ boxes,
    const float* __restrict__ gt_boxes,
    const int* __restrict__ gt_labels,
    float* __restrict__ out)
{
    const int b = blockIdx.x;
    const int t = threadIdx.x;
    const int lane = t & 31;
    const int w = t >> 5;

    __shared__ unsigned long long T[1024];
    __shared__ __align__(16) unsigned char ubuf[8192];   // CLIST (4KB) + RANKS (4KB)
    __shared__ float sx1[1024], sy1[1024], sx2[1024], sy2[1024], stopv[1024];
    __shared__ int scls[1024], skeep[1024];
    __shared__ int scount[CQ], scoff[CQ + 1];
    __shared__ float sm_iou[GQ], sm_conf[GQ], sm_m[GQ];

    int* CLIST = reinterpret_cast<int*>(ubuf);
    int* RANKS = reinterpret_cast<int*>(ubuf + 4096);

    // ---- Phase 1: top-1024 selection via bitonic merges ----
    T[t] = __ldg(&g_keys[b * NPAD + t]);   // chunk 0, already desc

    for (int ch = 1; ch < NCHUNK; ++ch) {
        // read chunk reversed -> ascending sequence
        unsigned long long cv = __ldg(&g_keys[b * NPAD + ch * 1024 + (1023 - t)]);
        __syncthreads();                    // previous merge complete
        unsigned long long tv = T[t];
        T[t] = (tv > cv) ? tv : cv;         // top half of bitonic split -> bitonic
        for (int j = 512; j > 0; j >>= 1) { // bitonic merge, descending
            __syncthreads();
            if (t < 512) {
                int i = ((t & ~(j - 1)) << 1) | (t & (j - 1));
                int p = i | j;
                unsigned long long a = T[i], bb = T[p];
                if (a < bb) { T[i] = bb; T[p] = a; }
            }
        }
    }
    __syncthreads();

    // ---- Phase 2: extract top-K candidates ----
    if (t < KQ) {
        unsigned long long key = T[t];
        float conf = __uint_as_float((unsigned int)(key >> 32));
        int idx = 0xFFFF - (int)((key >> 16) & 0xFFFFu);
        int cl = (int)((key >> 8) & 0xFFu);
        if ((unsigned)idx >= (unsigned)NQ) idx = 0;   // (pads can't reach top-K; safety)
        float4 bb = __ldg(reinterpret_cast<const float4*>(boxes) + (size_t)b * NQ + idx);
        float hw = 0.5f * bb.z, hh = 0.5f * bb.w;
        sx1[t] = bb.x - hw; sy1[t] = bb.y - hh;
        sx2[t] = bb.x + hw; sy2[t] = bb.y + hh;
        stopv[t] = conf;
        scls[t] = cl;
        skeep[t] = (conf > 0.0f) ? 1 : 0;
    } else {
        stopv[t] = 0.0f; scls[t] = -1; skeep[t] = 0;
        sx1[t] = sy1[t] = sx2[t] = sy2[t] = 0.0f;
    }
    if (t < CQ) scount[t] = 0;
    __syncthreads();

    // ---- Phase 3: stable per-class ranks (warp 0, ballot-based counting) ----
    if (w == 0) {
        for (int base = 0; base < KQ; base += 32) {
            int j = base + lane;
            int c = (j < KQ) ? scls[j] : -(lane + 2);   // distinct negatives -> singleton groups
            unsigned mask = __match_any_sync(0xFFFFFFFFu, c);
            int leader = __ffs(mask) - 1;
            int rin = __popc(mask & ((1u << lane) - 1u));
            int baseCnt = 0;
            if (lane == leader && j < KQ) {
                baseCnt = scount[c];
                scount[c] = baseCnt + __popc(mask);
            }
            baseCnt = __shfl_sync(0xFFFFFFFFu, baseCnt, leader);
            if (j < KQ) RANKS[j] = baseCnt + rin;
            __syncwarp();
        }
    }
    __syncthreads();

    if (t == 0) {
        int acc = 0;
        for (int c = 0; c < CQ; ++c) { scoff[c] = acc; acc += scount[c]; }
        scoff[CQ] = acc;
    }
    __syncthreads();
    if (t < KQ) CLIST[scoff[scls[t]] + RANKS[t]] = t;
    __syncthreads();

    // ---- Phase 4: per-class greedy NMS (classes independent) ----
    for (int c = w; c < CQ; c += 32) {
        int base = scoff[c];
        int mm = scount[c];
        for (int i = 0; i < mm; ++i) {
            int gi = CLIST[base + i];
            if (skeep[gi]) {
                float ax1 = sx1[gi], ay1 = sy1[gi], ax2 = sx2[gi], ay2 = sy2[gi];
                float areaA = (ax2 - ax1) * (ay2 - ay1);
                for (int jj = i + 1 + lane; jj < mm; jj += 32) {
                    int gj = CLIST[base + jj];
                    if (skeep[gj]) {
                        float x1 = fmaxf(ax1, sx1[gj]);
                        float y1 = fmaxf(ay1, sy1[gj]);
                        float x2 = fminf(ax2, sx2[gj]);
                        float y2 = fminf(ay2, sy2[gj]);
                        float inter = fmaxf(x2 - x1, 0.0f) * fmaxf(y2 - y1, 0.0f);
                        float areaB = (sx2[gj] - sx1[gj]) * (sy2[gj] - sy1[gj]);
                        float iou = inter / (areaA + areaB - inter + EPSQ);
                        if (iou > NMS_IOU) skeep[gj] = 0;
                    }
                }
            }
            __syncwarp();
        }
    }
    __syncthreads();

    // ---- Phase 5: GT matching (one warp per GT) ----
    if (w < GQ) {
        int g = w;
        float4 gb = __ldg(reinterpret_cast<const float4*>(gt_boxes) + (size_t)b * GQ + g);
        int gl = __ldg(gt_labels + b * GQ + g);
        float areaG = (gb.z - gb.x) * (gb.w - gb.y);

        float bestv = -3.0e38f;
        int bestj = 0x7FFFFFFF;
        for (int j = lane; j < KQ; j += 32) {
            float v = -1.0f;
            if (skeep[j] && scls[j] == gl) {
                float x1 = fmaxf(sx1[j], gb.x);
                float y1 = fmaxf(sy1[j], gb.y);
                float x2 = fminf(sx2[j], gb.z);
                float y2 = fminf(sy2[j], gb.w);
                float inter = fmaxf(x2 - x1, 0.0f) * fmaxf(y2 - y1, 0.0f);
                float areaJ = (sx2[j] - sx1[j]) * (sy2[j] - sy1[j]);
                v = inter / (areaJ + areaG - inter + EPSQ);
            }
            if (v > bestv || (v == bestv && j < bestj)) { bestv = v; bestj = j; }
        }
        for (int o = 16; o > 0; o >>= 1) {
            float ov = __shfl_down_sync(0xFFFFFFFFu, bestv, o);
            int oj = __shfl_down_sync(0xFFFFFFFFu, bestj, o);
            if (ov > bestv || (ov == bestv && oj < bestj)) { bestv = ov; bestj = oj; }
        }
        if (lane == 0) {
            float bconf = stopv[bestj];
            float matched = (bestv > MATCH_IOU && bconf > MATCH_CONF) ? 1.0f : 0.0f;
            out[b * GQ + g] = bestv;                    // best_iou
            out[BQ * GQ + b * GQ + g] = bconf;          // best_conf
            out[2 * BQ * GQ + b * GQ + g] = matched;    // matched
            sm_iou[g] = bestv; sm_conf[g] = bconf; sm_m[g] = matched;
        }
    }
    __syncthreads();

    // ---- Phase 6: per-image stats (warp 0) ----
    if (w == 0) {
        float f = (lane < GQ) ? sm_m[lane] : 0.0f;
        float si = (lane < GQ) ? sm_iou[lane] * f : 0.0f;
        float sc = (lane < GQ) ? sm_conf[lane] * f : 0.0f;
        for (int o = 16; o > 0; o >>= 1) {
            f  += __shfl_xor_sync(0xFFFFFFFFu, f, o);
            si += __shfl_xor_sync(0xFFFFFFFFu, si, o);
            sc += __shfl_xor_sync(0xFFFFFFFFu, sc, o);
        }
        if (lane == 0) {
            float denom = fmaxf(f, 1.0f);
            float* st = out + 3 * BQ * GQ + b * 3;
            st[0] = si / denom;
            st[1] = sc / denom;
            st[2] = f / (float)GQ;
        }
    }
}

extern "C" void kernel_launch(void* const* d_in, const int* in_sizes, int n_in,
                              void* d_out, int out_size) {
    // identify inputs by element count (robust to ordering)
    const float* boxes = nullptr;
    const float* scores = nullptr;
    const float* gtb = nullptr;
    const int* gtl = nullptr;
    for (int i = 0; i < n_in; ++i) {
        int sz = in_sizes[i];
        if (sz == BQ * NQ * CQ)      scores = (const float*)d_in[i];
        else if (sz == BQ * NQ * 4)  boxes = (const float*)d_in[i];
        else if (sz == BQ * GQ * 4)  gtb = (const float*)d_in[i];
        else if (sz == BQ * GQ)      gtl = (const int*)d_in[i];
    }
    float* out = (float*)d_out;

    score_sort_kernel<<<BQ * NCHUNK, 1024>>>(scores);
    select_nms_match_kernel<<<BQ, 1024>>>(boxes, gtb, gtl, out);
}

// round 2
// speedup vs baseline: 1.1757x; 1.1757x over previous
#include <cuda_runtime.h>
#include <cstdint>

using u64 = unsigned long long;

#define BQ 16
#define NQ 8400
#define CQ 80
#define GQ 20
#define KQ 1000
#define NPAD 9216          // 9 * 1024
#define NCHUNK 9
#define F4_PER_IMG (NQ * 20)   // 168000 float4 per image in scores

#define CONF_THRES 0.25f
#define NMS_IOU 0.45f
#define MATCH_IOU 0.6f
#define MATCH_CONF 0.5f
#define EPSQ 1e-7f

// scratch buffers (merge tree)
__device__ u64 g_keys[BQ * NPAD];        // sorted 1024-chunks, 9 per image
__device__ u64 g_l1[BQ * 4 * 1024];      // level-1 merge results
__device__ u64 g_l2[BQ * 2 * 1024];      // level-2 merge results

__device__ __forceinline__ u64 bsel(u64 a, u64 b, bool takeMax) {
    return takeMax ? (a > b ? a : b) : (a < b ? a : b);
}

// one compare-exchange stage within a warp (j <= 16)
__device__ __forceinline__ void warp_stage(u64& val, int t, int k, int j) {
    u64 o = __shfl_xor_sync(0xFFFFFFFFu, val, j);
    bool takeMax = (((t & k) == 0) == ((t & j) == 0));
    val = bsel(val, o, takeMax);
}

// full bitonic sort of 1024 u64 (descending), value in register, sh = 1024-entry exchange buffer
__device__ __forceinline__ void bitonic_sort_1024(u64& val, u64* sh, int t) {
#pragma unroll
    for (int k = 2; k <= 32; k <<= 1)
#pragma unroll
        for (int j = k >> 1; j > 0; j >>= 1) warp_stage(val, t, k, j);
#pragma unroll
    for (int k = 64; k <= 1024; k <<= 1) {
#pragma unroll
        for (int j = k >> 1; j >= 32; j >>= 1) {
            sh[t] = val; __syncthreads();
            u64 o = sh[t ^ j];
            bool tm = (((t & k) == 0) == ((t & j) == 0));
            val = bsel(val, o, tm);
            __syncthreads();
        }
#pragma unroll
        for (int j = 16; j > 0; j >>= 1) warp_stage(val, t, k, j);
    }
}

// bitonic merge (input bitonic across 1024 threads) -> descending sorted
__device__ __forceinline__ void bitonic_merge_desc(u64& val, u64* sh, int t) {
#pragma unroll
    for (int j = 512; j >= 32; j >>= 1) {
        sh[t] = val; __syncthreads();
        u64 o = sh[t ^ j];
        val = bsel(val, o, (t & j) == 0);
        __syncthreads();
    }
#pragma unroll
    for (int j = 16; j > 0; j >>= 1) {
        u64 o = __shfl_xor_sync(0xFFFFFFFFu, val, j);
        val = bsel(val, o, (t & j) == 0);
    }
}

// ---------------------------------------------------------------------------
// Kernel A: coalesced scores read via smem staging, per-anchor max/argmax key,
// hybrid bitonic sort of each 1024-anchor chunk. 144 blocks x 1024 threads.
// dynamic smem: tile 256x84 floats (86016B) + keys 1024 u64 (8192B) = 94208B
// ---------------------------------------------------------------------------
__global__ void __launch_bounds__(1024) score_sort_kernel(const float* __restrict__ scores) {
    extern __shared__ float dsm[];
    float* tile = dsm;                              // [256][84]
    u64* keys = (u64*)(dsm + 256 * 84);             // [1024]

    const int blk = blockIdx.x;
    const int b = blk / NCHUNK;
    const int ch = blk % NCHUNK;
    const int t = threadIdx.x;

    const float4* src = reinterpret_cast<const float4*>(scores) + (size_t)b * F4_PER_IMG;

    for (int s = 0; s < 4; ++s) {
        const int base = (ch * 1024 + s * 256) * 20;
        // coalesced load of 256 rows x 80 floats
#pragma unroll
        for (int i = 0; i < 5; ++i) {
            int l = i * 1024 + t;          // 0..5119
            int f4 = base + l;
            float4 v = make_float4(0.f, 0.f, 0.f, 0.f);
            if (f4 < F4_PER_IMG) v = __ldg(src + f4);
            int r = l / 20, c4 = l - r * 20;
            *reinterpret_cast<float4*>(&tile[r * 84 + c4 * 4]) = v;
        }
        __syncthreads();

        // 4 lanes per row reduce max/argmax (strictly-first tie rule)
        int row = t >> 2, q = t & 3;
        float best = -1.0f; int bc = 0;
#pragma unroll
        for (int i = 0; i < 5; ++i) {
            float4 v = *reinterpret_cast<const float4*>(&tile[row * 84 + q * 20 + i * 4]);
            int cb = q * 20 + i * 4;
            if (v.x > best) { best = v.x; bc = cb; }
            if (v.y > best) { best = v.y; bc = cb + 1; }
            if (v.z > best) { best = v.z; bc = cb + 2; }
            if (v.w > best) { best = v.w; bc = cb + 3; }
        }
        // pack so max => larger conf, tie => smaller col
        u64 pk = ((u64)__float_as_uint(best) << 32) | (u64)(unsigned)(127 - bc);
        { u64 o = __shfl_xor_sync(0xFFFFFFFFu, pk, 1); pk = pk > o ? pk : o; }
        { u64 o = __shfl_xor_sync(0xFFFFFFFFu, pk, 2); pk = pk > o ? pk : o; }
        if (q == 0) {
            float f = __uint_as_float((unsigned)(pk >> 32));
            int col = 127 - (int)(pk & 0xFFFFFFFFu);
            float conf = (f >= CONF_THRES) ? f : 0.0f;
            int n = ch * 1024 + s * 256 + row;
            keys[s * 256 + row] = ((u64)__float_as_uint(conf) << 32)
                                | ((u64)(0xFFFFu - (unsigned)n) << 16)
                                | ((u64)(unsigned)col << 8);
        }
        __syncthreads();
    }

    u64 val = keys[t];
    bitonic_sort_1024(val, keys, t);
    g_keys[(size_t)b * NPAD + ch * 1024 + t] = val;
}

// ---------------------------------------------------------------------------
// Merge level kernels: merge two sorted-desc 1024 lists -> top-1024 sorted desc
// level 0: g_keys chunks (0,1)(2,3)(4,5)(6,7) -> g_l1   (64 blocks)
// level 1: g_l1 (0,1)(2,3) -> g_l2                      (32 blocks)
// ---------------------------------------------------------------------------
__global__ void __launch_bounds__(1024) merge_kernel(int level) {
    __shared__ u64 sh[1024];
    const int t = threadIdx.x;
    const u64* A;
    u64* dst;
    if (level == 0) {
        int b = blockIdx.x >> 2, p = blockIdx.x & 3;
        A = g_keys + (size_t)b * NPAD + (2 * p) * 1024;
        dst = g_l1 + ((size_t)b * 4 + p) * 1024;
    } else {
        int b = blockIdx.x >> 1, p = blockIdx.x & 1;
        A = g_l1 + ((size_t)b * 4 + 2 * p) * 1024;
        dst = g_l2 + ((size_t)b * 2 + p) * 1024;
    }
    u64 val = __ldg(A + t);
    u64 cv = __ldg(A + 1024 + (1023 - t));   // reversed second list -> bitonic
    val = val > cv ? val : cv;               // top half of 2048 bitonic split
    bitonic_merge_desc(val, sh, t);
    dst[t] = val;
}

// ---------------------------------------------------------------------------
// Final kernel: 2 serial merges (l2 halves, then chunk 8), extract top-K,
// parallel per-class ranks, per-class greedy NMS, GT match + stats.
// 16 blocks x 1024 threads.
// ---------------------------------------------------------------------------
__global__ void __launch_bounds__(1024) final_kernel(
    const float* __restrict__ boxes,
    const float* __restrict__ gt_boxes,
    const int* __restrict__ gt_labels,
    float* __restrict__ out)
{
    const int b = blockIdx.x;
    const int t = threadIdx.x;
    const int lane = t & 31;
    const int w = t >> 5;

    __shared__ u64 sh[1024];                       // 8KB merge exchange
    __shared__ float sx1[1024], sy1[1024], sx2[1024], sy2[1024], stopv[1024]; // 20KB
    __shared__ unsigned char scls[1024], skeep[1024];                         // 2KB
    __shared__ int wcnt[32][CQ];                   // 10.24KB per-warp class counts
    __shared__ int scount[CQ];
    __shared__ int scanbuf[128];
    __shared__ unsigned short CLIST[1024];         // 2KB
    __shared__ float sm_iou[GQ], sm_conf[GQ], sm_m[GQ];

    // init per-warp histogram (barrier coverage provided by merge stages below)
    for (int i = t; i < 32 * CQ; i += 1024) ((int*)wcnt)[i] = 0;

    // ---- merges: (l2[0] U l2[1]) then U chunk8 ----
    u64 val = __ldg(g_l2 + ((size_t)b * 2) * 1024 + t);
    {
        u64 cv = __ldg(g_l2 + ((size_t)b * 2 + 1) * 1024 + (1023 - t));
        val = val > cv ? val : cv;
    }
    bitonic_merge_desc(val, sh, t);
    {
        u64 cv = __ldg(g_keys + (size_t)b * NPAD + 8 * 1024 + (1023 - t));
        val = val > cv ? val : cv;
    }
    bitonic_merge_desc(val, sh, t);

    // ---- extract top-K candidates (own key in register) ----
    int myc;
    if (t < KQ) {
        float conf = __uint_as_float((unsigned)(val >> 32));
        int idx = 0xFFFF - (int)((val >> 16) & 0xFFFFu);
        int cl = (int)((val >> 8) & 0xFFu);
        if ((unsigned)idx >= (unsigned)NQ) idx = 0;
        float4 bb = __ldg(reinterpret_cast<const float4*>(boxes) + (size_t)b * NQ + idx);
        float hw = 0.5f * bb.z, hh = 0.5f * bb.w;
        sx1[t] = bb.x - hw; sy1[t] = bb.y - hh;
        sx2[t] = bb.x + hw; sy2[t] = bb.y + hh;
        stopv[t] = conf;
        scls[t] = (unsigned char)cl;
        skeep[t] = (conf > 0.0f) ? 1 : 0;
        myc = cl;
    } else {
        stopv[t] = 0.0f; scls[t] = 0; skeep[t] = 0;
        sx1[t] = sy1[t] = sx2[t] = sy2[t] = 0.0f;
        myc = 0x100 + lane;   // distinct -> singleton match groups
    }

    // ---- parallel stable per-class ranks ----
    unsigned mask = __match_any_sync(0xFFFFFFFFu, myc);
    int rin = __popc(mask & ((1u << lane) - 1u));
    int leader = __ffs(mask) - 1;
    if (lane == leader && t < KQ) wcnt[w][myc] = __popc(mask);
    __syncthreads();

    // per-class: exclusive prefix across warps + total
    if (t < CQ) {
        int acc = 0;
#pragma unroll
        for (int w2 = 0; w2 < 32; ++w2) {
            int x = wcnt[w2][t];
            wcnt[w2][t] = acc;
            acc += x;
        }
        scount[t] = acc;
    }
    if (t < 128) scanbuf[t] = 0;
    __syncthreads();
    if (t < CQ) scanbuf[t] = scount[t];
    __syncthreads();
    // Hillis-Steele inclusive scan over 128 (classes padded with 0)
#pragma unroll
    for (int off = 1; off < 128; off <<= 1) {
        int v = 0;
        if (t < 128 && t >= off) v = scanbuf[t - off];
        __syncthreads();
        if (t < 128) scanbuf[t] += v;
        __syncthreads();
    }
    if (t < KQ) {
        int base = scanbuf[myc] - scount[myc];
        CLIST[base + wcnt[w][myc] + rin] = (unsigned short)t;
    }
    __syncthreads();

    // ---- per-class greedy NMS (classes independent under MAX_WH offset) ----
    for (int c = w; c < CQ; c += 32) {
        int base = scanbuf[c] - scount[c];
        int mm = scount[c];
        for (int i = 0; i < mm; ++i) {
            int gi = CLIST[base + i];
            if (skeep[gi]) {
                float ax1 = sx1[gi], ay1 = sy1[gi], ax2 = sx2[gi], ay2 = sy2[gi];
                float areaA = (ax2 - ax1) * (ay2 - ay1);
                for (int jj = i + 1 + lane; jj < mm; jj += 32) {
                    int gj = CLIST[base + jj];
                    if (skeep[gj]) {
                        float x1 = fmaxf(ax1, sx1[gj]);
                        float y1 = fmaxf(ay1, sy1[gj]);
                        float x2 = fminf(ax2, sx2[gj]);
                        float y2 = fminf(ay2, sy2[gj]);
                        float inter = fmaxf(x2 - x1, 0.0f) * fmaxf(y2 - y1, 0.0f);
                        float areaB = (sx2[gj] - sx1[gj]) * (sy2[gj] - sy1[gj]);
                        float iou = inter / (areaA + areaB - inter + EPSQ);
                        if (iou > NMS_IOU) skeep[gj] = 0;
                    }
                }
            }
            __syncwarp();
        }
    }
    __syncthreads();

    // ---- GT matching (one warp per GT) ----
    if (w < GQ) {
        int g = w;
        float4 gb = __ldg(reinterpret_cast<const float4*>(gt_boxes) + (size_t)b * GQ + g);
        int gl = __ldg(gt_labels + b * GQ + g);
        float areaG = (gb.z - gb.x) * (gb.w - gb.y);

        float bestv = -3.0e38f;
        int bestj = 0x7FFFFFFF;
        for (int j = lane; j < KQ; j += 32) {
            float v = -1.0f;
            if (skeep[j] && (int)scls[j] == gl) {
                float x1 = fmaxf(sx1[j], gb.x);
                float y1 = fmaxf(sy1[j], gb.y);
                float x2 = fminf(sx2[j], gb.z);
                float y2 = fminf(sy2[j], gb.w);
                float inter = fmaxf(x2 - x1, 0.0f) * fmaxf(y2 - y1, 0.0f);
                float areaJ = (sx2[j] - sx1[j]) * (sy2[j] - sy1[j]);
                v = inter / (areaJ + areaG - inter + EPSQ);
            }
            if (v > bestv || (v == bestv && j < bestj)) { bestv = v; bestj = j; }
        }
#pragma unroll
        for (int o = 16; o > 0; o >>= 1) {
            float ov = __shfl_down_sync(0xFFFFFFFFu, bestv, o);
            int oj = __shfl_down_sync(0xFFFFFFFFu, bestj, o);
            if (ov > bestv || (ov == bestv && oj < bestj)) { bestv = ov; bestj = oj; }
        }
        if (lane == 0) {
            float bconf = stopv[bestj];
            float matched = (bestv > MATCH_IOU && bconf > MATCH_CONF) ? 1.0f : 0.0f;
            out[b * GQ + g] = bestv;
            out[BQ * GQ + b * GQ + g] = bconf;
            out[2 * BQ * GQ + b * GQ + g] = matched;
            sm_iou[g] = bestv; sm_conf[g] = bconf; sm_m[g] = matched;
        }
    }
    __syncthreads();

    // ---- per-image stats ----
    if (w == 0) {
        float f = (lane < GQ) ? sm_m[lane] : 0.0f;
        float si = (lane < GQ) ? sm_iou[lane] * f : 0.0f;
        float sc = (lane < GQ) ? sm_conf[lane] * f : 0.0f;
#pragma unroll
        for (int o = 16; o > 0; o >>= 1) {
            f  += __shfl_xor_sync(0xFFFFFFFFu, f, o);
            si += __shfl_xor_sync(0xFFFFFFFFu, si, o);
            sc += __shfl_xor_sync(0xFFFFFFFFu, sc, o);
        }
        if (lane == 0) {
            float denom = fmaxf(f, 1.0f);
            float* st = out + 3 * BQ * GQ + b * 3;
            st[0] = si / denom;
            st[1] = sc / denom;
            st[2] = f / (float)GQ;
        }
    }
}

extern "C" void kernel_launch(void* const* d_in, const int* in_sizes, int n_in,
                              void* d_out, int out_size) {
    const float* boxes = nullptr;
    const float* scores = nullptr;
    const float* gtb = nullptr;
    const int* gtl = nullptr;
    for (int i = 0; i < n_in; ++i) {
        int sz = in_sizes[i];
        if (sz == BQ * NQ * CQ)      scores = (const float*)d_in[i];
        else if (sz == BQ * NQ * 4)  boxes = (const float*)d_in[i];
        else if (sz == BQ * GQ * 4)  gtb = (const float*)d_in[i];
        else if (sz == BQ * GQ)      gtl = (const int*)d_in[i];
    }
    float* out = (float*)d_out;

    const int SMEM_A = 256 * 84 * 4 + 1024 * 8;   // 94208 bytes
    cudaFuncSetAttribute(score_sort_kernel, cudaFuncAttributeMaxDynamicSharedMemorySize, SMEM_A);

    score_sort_kernel<<<BQ * NCHUNK, 1024, SMEM_A>>>(scores);
    merge_kernel<<<BQ * 4, 1024>>>(0);
    merge_kernel<<<BQ * 2, 1024>>>(1);
    final_kernel<<<BQ, 1024>>>(boxes, gtb, gtl, out);
}

// round 3
// speedup vs baseline: 1.2539x; 1.0665x over previous
#include <cuda_runtime.h>
#include <cstdint>

using u64 = unsigned long long;

#define BQ 16
#define NQ 8400
#define CQ 80
#define GQ 20
#define KQ 1000
#define NPAD 9216          // 9 * 1024
#define NCHUNK 9
#define F4_PER_IMG (NQ * 20)

#define CONF_THRES 0.25f
#define NMS_IOU 0.45f
#define MATCH_IOU 0.6f
#define MATCH_CONF 0.5f
#define EPSQ 1e-7f

// merge-tree scratch
__device__ u64 g_keys[BQ * NPAD];
__device__ u64 g_l1[BQ * 4 * 1024];
__device__ u64 g_l2[BQ * 2 * 1024];
// per-image candidate SoA (sorted position 0..1023)
__device__ float gx1[BQ * 1024], gy1[BQ * 1024], gx2[BQ * 1024], gy2[BQ * 1024];
__device__ float gconf[BQ * 1024];
__device__ int   gcls[BQ * 1024], gkeep[BQ * 1024], gclist[BQ * 1024];
__device__ int   gbase[BQ * CQ], gcnt[BQ * CQ];

__device__ __forceinline__ u64 bsel(u64 a, u64 b, bool takeMax) {
    return takeMax ? (a > b ? a : b) : (a < b ? a : b);
}

__device__ __forceinline__ void warp_stage(u64& val, int t, int k, int j) {
    u64 o = __shfl_xor_sync(0xFFFFFFFFu, val, j);
    bool takeMax = (((t & k) == 0) == ((t & j) == 0));
    val = bsel(val, o, takeMax);
}

__device__ __forceinline__ void bitonic_sort_1024(u64& val, u64* sh, int t) {
#pragma unroll
    for (int k = 2; k <= 32; k <<= 1)
#pragma unroll
        for (int j = k >> 1; j > 0; j >>= 1) warp_stage(val, t, k, j);
#pragma unroll
    for (int k = 64; k <= 1024; k <<= 1) {
#pragma unroll
        for (int j = k >> 1; j >= 32; j >>= 1) {
            sh[t] = val; __syncthreads();
            u64 o = sh[t ^ j];
            bool tm = (((t & k) == 0) == ((t & j) == 0));
            val = bsel(val, o, tm);
            __syncthreads();
        }
#pragma unroll
        for (int j = 16; j > 0; j >>= 1) warp_stage(val, t, k, j);
    }
}

__device__ __forceinline__ void bitonic_merge_desc(u64& val, u64* sh, int t) {
#pragma unroll
    for (int j = 512; j >= 32; j >>= 1) {
        sh[t] = val; __syncthreads();
        u64 o = sh[t ^ j];
        val = bsel(val, o, (t & j) == 0);
        __syncthreads();
    }
#pragma unroll
    for (int j = 16; j > 0; j >>= 1) {
        u64 o = __shfl_xor_sync(0xFFFFFFFFu, val, j);
        val = bsel(val, o, (t & j) == 0);
    }
}

// ---------------------------------------------------------------------------
// K1: coalesced scores read, per-anchor max/argmax key, chunk bitonic sort.
// ---------------------------------------------------------------------------
__global__ void __launch_bounds__(1024) score_sort_kernel(const float* __restrict__ scores) {
    extern __shared__ float dsm[];
    float* tile = dsm;                              // [256][84]
    u64* keys = (u64*)(dsm + 256 * 84);

    const int blk = blockIdx.x;
    const int b = blk / NCHUNK;
    const int ch = blk % NCHUNK;
    const int t = threadIdx.x;

    const float4* src = reinterpret_cast<const float4*>(scores) + (size_t)b * F4_PER_IMG;

    for (int s = 0; s < 4; ++s) {
        const int base = (ch * 1024 + s * 256) * 20;
#pragma unroll
        for (int i = 0; i < 5; ++i) {
            int l = i * 1024 + t;
            int f4 = base + l;
            float4 v = make_float4(0.f, 0.f, 0.f, 0.f);
            if (f4 < F4_PER_IMG) v = __ldg(src + f4);
            int r = l / 20, c4 = l - r * 20;
            *reinterpret_cast<float4*>(&tile[r * 84 + c4 * 4]) = v;
        }
        __syncthreads();

        int row = t >> 2, q = t & 3;
        float best = -1.0f; int bc = 0;
#pragma unroll
        for (int i = 0; i < 5; ++i) {
            float4 v = *reinterpret_cast<const float4*>(&tile[row * 84 + q * 20 + i * 4]);
            int cb = q * 20 + i * 4;
            if (v.x > best) { best = v.x; bc = cb; }
            if (v.y > best) { best = v.y; bc = cb + 1; }
            if (v.z > best) { best = v.z; bc = cb + 2; }
            if (v.w > best) { best = v.w; bc = cb + 3; }
        }
        u64 pk = ((u64)__float_as_uint(best) << 32) | (u64)(unsigned)(127 - bc);
        { u64 o = __shfl_xor_sync(0xFFFFFFFFu, pk, 1); pk = pk > o ? pk : o; }
        { u64 o = __shfl_xor_sync(0xFFFFFFFFu, pk, 2); pk = pk > o ? pk : o; }
        if (q == 0) {
            float f = __uint_as_float((unsigned)(pk >> 32));
            int col = 127 - (int)(pk & 0xFFFFFFFFu);
            float conf = (f >= CONF_THRES) ? f : 0.0f;
            int n = ch * 1024 + s * 256 + row;
            keys[s * 256 + row] = ((u64)__float_as_uint(conf) << 32)
                                | ((u64)(0xFFFFu - (unsigned)n) << 16)
                                | ((u64)(unsigned)col << 8);
        }
        __syncthreads();
    }

    u64 val = keys[t];
    bitonic_sort_1024(val, keys, t);
    g_keys[(size_t)b * NPAD + ch * 1024 + t] = val;
}

// ---------------------------------------------------------------------------
// K2/K3: merge two sorted-desc 1024 lists -> top-1024
// ---------------------------------------------------------------------------
__global__ void __launch_bounds__(1024) merge_kernel(int level) {
    __shared__ u64 sh[1024];
    const int t = threadIdx.x;
    const u64* A;
    u64* dst;
    if (level == 0) {
        int b = blockIdx.x >> 2, p = blockIdx.x & 3;
        A = g_keys + (size_t)b * NPAD + (2 * p) * 1024;
        dst = g_l1 + ((size_t)b * 4 + p) * 1024;
    } else {
        int b = blockIdx.x >> 1, p = blockIdx.x & 1;
        A = g_l1 + ((size_t)b * 4 + 2 * p) * 1024;
        dst = g_l2 + ((size_t)b * 2 + p) * 1024;
    }
    u64 val = __ldg(A + t);
    u64 cv = __ldg(A + 1024 + (1023 - t));
    val = val > cv ? val : cv;
    bitonic_merge_desc(val, sh, t);
    dst[t] = val;
}

// ---------------------------------------------------------------------------
// K4: final merges + extract top-K to gmem SoA + per-class partition.
// 16 blocks x 1024.
// ---------------------------------------------------------------------------
__global__ void __launch_bounds__(1024) partition_kernel(const float* __restrict__ boxes) {
    const int b = blockIdx.x;
    const int t = threadIdx.x;
    const int lane = t & 31;
    const int w = t >> 5;

    __shared__ u64 sh[1024];
    __shared__ int wcnt[32][CQ];
    __shared__ int scount[CQ], sbase[CQ];

    for (int i = t; i < 32 * CQ; i += 1024) ((int*)wcnt)[i] = 0;

    u64 val = __ldg(g_l2 + ((size_t)b * 2) * 1024 + t);
    {
        u64 cv = __ldg(g_l2 + ((size_t)b * 2 + 1) * 1024 + (1023 - t));
        val = val > cv ? val : cv;
    }
    bitonic_merge_desc(val, sh, t);
    {
        u64 cv = __ldg(g_keys + (size_t)b * NPAD + 8 * 1024 + (1023 - t));
        val = val > cv ? val : cv;
    }
    bitonic_merge_desc(val, sh, t);

    const int gb = b * 1024 + t;
    int myc;
    if (t < KQ) {
        float conf = __uint_as_float((unsigned)(val >> 32));
        int idx = 0xFFFF - (int)((val >> 16) & 0xFFFFu);
        int cl = (int)((val >> 8) & 0xFFu);
        if ((unsigned)idx >= (unsigned)NQ) idx = 0;
        float4 bb = __ldg(reinterpret_cast<const float4*>(boxes) + (size_t)b * NQ + idx);
        float hw = 0.5f * bb.z, hh = 0.5f * bb.w;
        gx1[gb] = bb.x - hw; gy1[gb] = bb.y - hh;
        gx2[gb] = bb.x + hw; gy2[gb] = bb.y + hh;
        gconf[gb] = conf;
        gcls[gb] = cl;
        gkeep[gb] = (conf > 0.0f) ? 1 : 0;
        myc = cl;
    } else {
        gconf[gb] = 0.0f; gcls[gb] = -1; gkeep[gb] = 0;
        myc = 0x100 + lane;
    }

    unsigned mask = __match_any_sync(0xFFFFFFFFu, myc);
    int rin = __popc(mask & ((1u << lane) - 1u));
    int leader = __ffs(mask) - 1;
    if (lane == leader && t < KQ) wcnt[w][myc] = __popc(mask);
    __syncthreads();

    if (t < CQ) {
        int acc = 0;
#pragma unroll
        for (int w2 = 0; w2 < 32; ++w2) {
            int x = wcnt[w2][t];
            wcnt[w2][t] = acc;
            acc += x;
        }
        scount[t] = acc;
    }
    __syncthreads();

    if (w == 0) {
        int carry = 0;
#pragma unroll
        for (int seg = 0; seg < 3; ++seg) {
            int c = seg * 32 + lane;
            int orig = (c < CQ) ? scount[c] : 0;
            int x = orig;
#pragma unroll
            for (int off = 1; off < 32; off <<= 1) {
                int y = __shfl_up_sync(0xFFFFFFFFu, x, off);
                if (lane >= off) x += y;
            }
            if (c < CQ) sbase[c] = carry + x - orig;
            carry += __shfl_sync(0xFFFFFFFFu, x, 31);
        }
    }
    __syncthreads();

    if (t < KQ) gclist[b * 1024 + sbase[myc] + wcnt[w][myc] + rin] = t;
    if (t < CQ) { gbase[b * CQ + t] = sbase[t]; gcnt[b * CQ + t] = scount[t]; }
}

// ---------------------------------------------------------------------------
// K5: per-class greedy NMS. grid = BQ*10 blocks x 256 threads (8 warps = 8
// classes per block, warp per class). Boxes live in lanes, shuffle broadcast.
// ---------------------------------------------------------------------------
__global__ void __launch_bounds__(256) nms_kernel() {
    const int b = blockIdx.x / 10;
    const int c = (blockIdx.x % 10) * 8 + (threadIdx.x >> 5);
    const int lane = threadIdx.x & 31;

    const int mm = gcnt[b * CQ + c];
    const int base = b * 1024 + gbase[b * CQ + c];
    if (mm <= 1) return;

    if (mm <= 32) {
        int pos = -1, alive = 0;
        float x1 = 0.f, y1 = 0.f, x2 = 0.f, y2 = 0.f;
        if (lane < mm) {
            pos = gclist[base + lane];
            int gi = b * 1024 + pos;
            x1 = gx1[gi]; y1 = gy1[gi]; x2 = gx2[gi]; y2 = gy2[gi];
            alive = gkeep[gi];
        }
        float area = (x2 - x1) * (y2 - y1);
        for (int i = 0; i < mm - 1; ++i) {
            int la = __shfl_sync(0xFFFFFFFFu, alive, i);
            float ax1 = __shfl_sync(0xFFFFFFFFu, x1, i);
            float ay1 = __shfl_sync(0xFFFFFFFFu, y1, i);
            float ax2 = __shfl_sync(0xFFFFFFFFu, x2, i);
            float ay2 = __shfl_sync(0xFFFFFFFFu, y2, i);
            float aarea = __shfl_sync(0xFFFFFFFFu, area, i);
            if (la && lane > i && alive) {
                float ix1 = fmaxf(ax1, x1);
                float iy1 = fmaxf(ay1, y1);
                float ix2 = fminf(ax2, x2);
                float iy2 = fminf(ay2, y2);
                float inter = fmaxf(ix2 - ix1, 0.0f) * fmaxf(iy2 - iy1, 0.0f);
                float iou = inter / (aarea + area - inter + EPSQ);
                if (iou > NMS_IOU) alive = 0;
            }
        }
        if (lane < mm) gkeep[b * 1024 + pos] = alive;
    } else {
        // rare fallback: generic warp loop over gmem
        for (int i = 0; i < mm; ++i) {
            int gi = b * 1024 + gclist[base + i];
            int ka = (lane == 0) ? gkeep[gi] : 0;
            ka = __shfl_sync(0xFFFFFFFFu, ka, 0);
            if (ka) {
                float ax1 = gx1[gi], ay1 = gy1[gi], ax2 = gx2[gi], ay2 = gy2[gi];
                float aarea = (ax2 - ax1) * (ay2 - ay1);
                for (int jj = i + 1 + lane; jj < mm; jj += 32) {
                    int gj = b * 1024 + gclist[base + jj];
                    if (gkeep[gj]) {
                        float x1 = fmaxf(ax1, gx1[gj]);
                        float y1 = fmaxf(ay1, gy1[gj]);
                        float x2 = fminf(ax2, gx2[gj]);
                        float y2 = fminf(ay2, gy2[gj]);
                        float inter = fmaxf(x2 - x1, 0.0f) * fmaxf(y2 - y1, 0.0f);
                        float areaB = (gx2[gj] - gx1[gj]) * (gy2[gj] - gy1[gj]);
                        float iou = inter / (aarea + areaB - inter + EPSQ);
                        if (iou > NMS_IOU) gkeep[gj] = 0;
                    }
                }
            }
            __syncwarp();
        }
    }
}

// ---------------------------------------------------------------------------
// K6: GT matching + stats. 16 blocks x 640 threads (warp per GT).
// ---------------------------------------------------------------------------
__global__ void __launch_bounds__(640) match_kernel(
    const float* __restrict__ gt_boxes,
    const int* __restrict__ gt_labels,
    float* __restrict__ out)
{
    const int b = blockIdx.x;
    const int t = threadIdx.x;
    const int lane = t & 31;
    const int g = t >> 5;    // 0..19

    __shared__ float sm_iou[GQ], sm_conf[GQ], sm_m[GQ];

    float4 gbx = __ldg(reinterpret_cast<const float4*>(gt_boxes) + (size_t)b * GQ + g);
    int gl = __ldg(gt_labels + b * GQ + g);
    float areaG = (gbx.z - gbx.x) * (gbx.w - gbx.y);

    float bestv = -3.0e38f;
    int bestj = 0x7FFFFFFF;
    const int ib = b * 1024;
    for (int j = lane; j < KQ; j += 32) {
        float v = -1.0f;
        if (gkeep[ib + j] && gcls[ib + j] == gl) {
            float x1 = fmaxf(gx1[ib + j], gbx.x);
            float y1 = fmaxf(gy1[ib + j], gbx.y);
            float x2 = fminf(gx2[ib + j], gbx.z);
            float y2 = fminf(gy2[ib + j], gbx.w);
            float inter = fmaxf(x2 - x1, 0.0f) * fmaxf(y2 - y1, 0.0f);
            float areaJ = (gx2[ib + j] - gx1[ib + j]) * (gy2[ib + j] - gy1[ib + j]);
            v = inter / (areaJ + areaG - inter + EPSQ);
        }
        if (v > bestv || (v == bestv && j < bestj)) { bestv = v; bestj = j; }
    }
#pragma unroll
    for (int o = 16; o > 0; o >>= 1) {
        float ov = __shfl_down_sync(0xFFFFFFFFu, bestv, o);
        int oj = __shfl_down_sync(0xFFFFFFFFu, bestj, o);
        if (ov > bestv || (ov == bestv && oj < bestj)) { bestv = ov; bestj = oj; }
    }
    if (lane == 0) {
        float bconf = gconf[ib + bestj];
        float matched = (bestv > MATCH_IOU && bconf > MATCH_CONF) ? 1.0f : 0.0f;
        out[b * GQ + g] = bestv;
        out[BQ * GQ + b * GQ + g] = bconf;
        out[2 * BQ * GQ + b * GQ + g] = matched;
        sm_iou[g] = bestv; sm_conf[g] = bconf; sm_m[g] = matched;
    }
    __syncthreads();

    if (g == 0) {
        float f = (lane < GQ) ? sm_m[lane] : 0.0f;
        float si = (lane < GQ) ? sm_iou[lane] * f : 0.0f;
        float sc = (lane < GQ) ? sm_conf[lane] * f : 0.0f;
#pragma unroll
        for (int o = 16; o > 0; o >>= 1) {
            f  += __shfl_xor_sync(0xFFFFFFFFu, f, o);
            si += __shfl_xor_sync(0xFFFFFFFFu, si, o);
            sc += __shfl_xor_sync(0xFFFFFFFFu, sc, o);
        }
        if (lane == 0) {
            float denom = fmaxf(f, 1.0f);
            float* st = out + 3 * BQ * GQ + b * 3;
            st[0] = si / denom;
            st[1] = sc / denom;
            st[2] = f / (float)GQ;
        }
    }
}

extern "C" void kernel_launch(void* const* d_in, const int* in_sizes, int n_in,
                              void* d_out, int out_size) {
    const float* boxes = nullptr;
    const float* scores = nullptr;
    const float* gtb = nullptr;
    const int* gtl = nullptr;
    for (int i = 0; i < n_in; ++i) {
        int sz = in_sizes[i];
        if (sz == BQ * NQ * CQ)      scores = (const float*)d_in[i];
        else if (sz == BQ * NQ * 4)  boxes = (const float*)d_in[i];
        else if (sz == BQ * GQ * 4)  gtb = (const float*)d_in[i];
        else if (sz == BQ * GQ)      gtl = (const int*)d_in[i];
    }
    float* out = (float*)d_out;

    const int SMEM_A = 256 * 84 * 4 + 1024 * 8;
    cudaFuncSetAttribute(score_sort_kernel, cudaFuncAttributeMaxDynamicSharedMemorySize, SMEM_A);

    score_sort_kernel<<<BQ * NCHUNK, 1024, SMEM_A>>>(scores);
    merge_kernel<<<BQ * 4, 1024>>>(0);
    merge_kernel<<<BQ * 2, 1024>>>(1);
    partition_kernel<<<BQ, 1024>>>(boxes);
    nms_kernel<<<BQ * 10, 256>>>();
    match_kernel<<<BQ, 640>>>(gtb, gtl, out);
}